// round 6
// baseline (speedup 1.0000x reference)
#include <cuda_runtime.h>
#include <cstdint>
#include <math.h>

// IMDCT, symmetry-halved GEMM, round 6: 128-thread blocks (all 4 SMSPs lit).
//
// z_col[j] = sum_f kr[j][f] * spec[b,f,col],  kr[j][f] = kernels[128+j][f]/(128*win[128+j])
//   out[b, s*256+k] = win[k]    *(k<128 ? -z_s[127-k]     : z_s[k-128])
//                   + win[k+256]*(k<128 ?  z_{s-1}[k+128] : z_{s-1}[383-k])
//
// Block = 128 threads = 2 groups of 64; group g handles spec-col window [32g, 32g+33]
// of a shared 66-col tile (NSEG=64 segments). Thread owns 4 z-rows x 17 col-pairs
// (fma.rn.f32x2). Halo cols computed by both groups (bit-identical, benign).
// 69.6KB dynamic smem -> 2 blocks/SM -> 2 warps/SMSP.

#define NFREQ    256
#define TFRAMES  4096
#define NSEG     64
#define SSTR     68         // spec tile row stride (words): 66 used cols + pad
#define LOUT     1048832
#define DSTR     256        // Dt row stride (words)
#define SMBYTES  (NFREQ * SSTR * 4)   // 69,632

#define FMA2(acc, a, v) \
    asm("fma.rn.f32x2 %0, %1, %2, %0;" : "+l"(acc) : "l"(a), "l"(v))
#define PACK2(dst, x) \
    asm("mov.b64 %0, {%1, %1};" : "=l"(dst) : "r"(__float_as_uint(x)))

__device__ float4 g_kt4[257 * 64];   // [f][t]: {kr(t),kr(t+64),kr(t+128),kr(t+192)}; 1 pad f-row
__device__ float  g_win[512];

static __device__ __forceinline__ float win_of(int t) {
    return sinf((float)M_PI * (float)(2 * t + 1) * (1.0f / 1024.0f));
}

__global__ void prep_kernel(const float* __restrict__ kernels)
{
    int idx = blockIdx.x * blockDim.x + threadIdx.x;   // 16384 threads
    if (idx < 512) g_win[idx] = win_of(idx);
    int f = idx & 255;
    int t = idx >> 8;                                  // 0..63
    const float s = 1.0f / 128.0f;
    float4 w;
    w.x = s * kernels[(128 + t      ) * 256 + f] / win_of(128 + t      );
    w.y = s * kernels[(128 + t +  64) * 256 + f] / win_of(128 + t +  64);
    w.z = s * kernels[(128 + t + 128) * 256 + f] / win_of(128 + t + 128);
    w.w = s * kernels[(128 + t + 192) * 256 + f] / win_of(128 + t + 192);
    g_kt4[f * 64 + t] = w;
}

__global__ __launch_bounds__(128, 2)
void imdct_main_kernel(const float* __restrict__ spec, float* __restrict__ out)
{
    extern __shared__ float sm[];                      // spec tile, reused as Dt

    const int tid = threadIdx.x;                       // 0..127
    const int lt  = tid & 63;
    const int g   = tid >> 6;                          // group 0/1
    const int b   = blockIdx.y;
    const int s0  = blockIdx.x * NSEG;

    // ---- Load spec cols c = s0-1 .. s0+64 (66 cols, zero-fill edges/pad) ----
    const float* specB = spec + (size_t)b * NFREQ * TFRAMES;
    for (int idx = tid; idx < NFREQ * SSTR; idx += 128) {
        int f = idx / SSTR;
        int j = idx - f * SSTR;
        int c = s0 - 1 + j;
        float v = 0.0f;
        if (j < 66 && c >= 0 && c < TFRAMES)
            v = specB[(size_t)f * TFRAMES + c];
        sm[idx] = v;
    }
    __syncthreads();

    // ---- Accumulators: 4 z-rows x 17 col-pairs over window [32g, 32g+33] ----
    unsigned long long acc[4][17];
    #pragma unroll
    for (int m = 0; m < 4; m++)
        #pragma unroll
        for (int p = 0; p < 17; p++) acc[m][p] = 0ull;

    const uint32_t sbase = (uint32_t)__cvta_generic_to_shared(sm) + (uint32_t)(g * 128);
    const float4* __restrict__ wp = g_kt4 + lt;

    float4 wc = wp[0];                                 // depth-1 prefetch

    #pragma unroll 1
    for (int f = 0; f < NFREQ; f++) {
        float4 wn = wp[(f + 1) * 64];

        unsigned long long w2[4];
        PACK2(w2[0], wc.x); PACK2(w2[1], wc.y);
        PACK2(w2[2], wc.z); PACK2(w2[3], wc.w);

        uint32_t srow = sbase + (uint32_t)(f * (SSTR * 4));
        #pragma unroll
        for (int q = 0; q < 8; q++) {
            unsigned long long v01, v23;               // window cols (4q,4q+1),(4q+2,4q+3)
            asm volatile("ld.shared.v2.b64 {%0, %1}, [%2];"
                         : "=l"(v01), "=l"(v23) : "r"(srow + q * 16));
            FMA2(acc[0][2*q], w2[0], v01);  FMA2(acc[0][2*q+1], w2[0], v23);
            FMA2(acc[1][2*q], w2[1], v01);  FMA2(acc[1][2*q+1], w2[1], v23);
            FMA2(acc[2][2*q], w2[2], v01);  FMA2(acc[2][2*q+1], w2[2], v23);
            FMA2(acc[3][2*q], w2[3], v01);  FMA2(acc[3][2*q+1], w2[3], v23);
        }
        unsigned long long vt;                         // window cols (32,33)
        asm volatile("ld.shared.b64 %0, [%1];" : "=l"(vt) : "r"(srow + 128));
        FMA2(acc[0][16], w2[0], vt);
        FMA2(acc[1][16], w2[1], vt);
        FMA2(acc[2][16], w2[2], vt);
        FMA2(acc[3][16], w2[3], vt);

        wc = wn;
    }

    // ---- Stage Dt[global_col][j]; global_col = 32g + local ----
    __syncthreads();                                   // done reading spec
    #pragma unroll
    for (int m = 0; m < 4; m++) {
        int j = lt + 64 * m;
        #pragma unroll
        for (int p = 0; p < 17; p++) {
            unsigned long long a = acc[m][p];
            sm[(32 * g + 2 * p)     * DSTR + j] = __uint_as_float((unsigned)a);
            sm[(32 * g + 2 * p + 1) * DSTR + j] = __uint_as_float((unsigned)(a >> 32));
        }
    }
    __syncthreads();

    // ---- Windowed overlap-add epilogue ----
    // Thread: 4 consecutive k (k0 = 4*lt), 32 segments (half = g).
    {
        const int k0 = 4 * lt;                         // 0..252
        const bool lo = (k0 < 128);                    // warp-uniform
        float wA[4], wB[4];
        #pragma unroll
        for (int d = 0; d < 4; d++) {
            int k = k0 + d;
            wA[d] = __ldg(&g_win[k]) * (lo ? -1.0f : 1.0f);
            wB[d] = __ldg(&g_win[k + 256]);
        }
        const int aOff = lo ? (124 - k0) : (k0 - 128); // word offset of zA quad
        const int bOff = lo ? (k0 + 128) : (380 - k0); // word offset of zB quad
        float* ob = out + (size_t)b * LOUT + k0;

        #pragma unroll 4
        for (int i = 0; i < 32; i++) {
            int s = s0 + 32 * g + i;
            if (s <= 4096) {
                int ci = 32 * g + i;                   // zB col; zA col = ci+1
                float4 a4 = *reinterpret_cast<const float4*>(sm + (ci + 1) * DSTR + aOff);
                float4 b4 = *reinterpret_cast<const float4*>(sm + ci * DSTR + bOff);
                float av[4], bv[4];
                if (lo) { av[0]=a4.w; av[1]=a4.z; av[2]=a4.y; av[3]=a4.x;
                          bv[0]=b4.x; bv[1]=b4.y; bv[2]=b4.z; bv[3]=b4.w; }
                else    { av[0]=a4.x; av[1]=a4.y; av[2]=a4.z; av[3]=a4.w;
                          bv[0]=b4.w; bv[1]=b4.z; bv[2]=b4.y; bv[3]=b4.x; }
                float4 o;
                o.x = wA[0] * av[0] + wB[0] * bv[0];
                o.y = wA[1] * av[1] + wB[1] * bv[1];
                o.z = wA[2] * av[2] + wB[2] * bv[2];
                o.w = wA[3] * av[3] + wB[3] * bv[3];
                *reinterpret_cast<float4*>(ob + (size_t)s * 256) = o;
            }
        }
    }
}

extern "C" void kernel_launch(void* const* d_in, const int* in_sizes, int n_in,
                              void* d_out, int out_size)
{
    const float* spec    = (const float*)d_in[0];   // [16,1,256,4096]
    const float* kernels = (const float*)d_in[1];   // [512,256]
    float* out = (float*)d_out;                     // [16,1048832]

    prep_kernel<<<64, 256>>>(kernels);              // 16384 threads

    cudaFuncSetAttribute(imdct_main_kernel,
                         cudaFuncAttributeMaxDynamicSharedMemorySize, SMBYTES);
    dim3 grid((4097 + NSEG - 1) / NSEG, 16);        // (65, 16)
    imdct_main_kernel<<<grid, 128, SMBYTES>>>(spec, out);
}